// round 5
// baseline (speedup 1.0000x reference)
#include <cuda_runtime.h>
#include <math.h>

#define GN_N_NODES 200000
#define GN_N_FEAT 256

// Scratch (device globals — zero-initialized BSS; no allocations allowed)
__device__ float g_h[GN_N_NODES];      // x @ W
__device__ float g_dis[GN_N_NODES];    // rsqrt(deg+1)
__device__ float g_a[GN_N_NODES];      // dis * h (scatter source)
__device__ float g_degacc[GN_N_NODES]; // edge-weight degree accumulator (kept zeroed)
__device__ int   g_is64;               // 1 if edge_index is int64, 0 if int32

// ---------------------------------------------------------------------------
// Kernel 0: detect edge_index dtype (int64 vs int32 stored in same buffer).
// ---------------------------------------------------------------------------
__global__ void k_detect(const long long* __restrict__ ei, int E, int N) {
    __shared__ int bad;
    if (threadIdx.x == 0) bad = 0;
    __syncthreads();
    int stride = E / 1024;
    for (int i = threadIdx.x; i < 1024; i += blockDim.x) {
        long long v = ei[(size_t)i * stride];
        if (v < 0 || v >= (long long)N) bad = 1;
    }
    __syncthreads();
    if (threadIdx.x == 0) g_is64 = bad ? 0 : 1;
}

// ---------------------------------------------------------------------------
// Fused kernel 1: GEMV blocks + degree-scatter blocks interleaved (Bresenham).
//   GEMV block: 8 warps, 1 node/warp:  h[n]=x[n,:]·W
//   DEG block : 256 thr × 8 edges:     degacc[col[e]] += attrs[e]
// ---------------------------------------------------------------------------
__global__ void k_fused1(const float* __restrict__ x,
                         const float* __restrict__ W,
                         float* __restrict__ h,
                         float* __restrict__ degacc,
                         int n_nodes,
                         const void* __restrict__ ei,
                         const float* __restrict__ attrs,
                         int E,
                         int nb_gemv, int nb_total) {
    long long b = blockIdx.x;
    long long before = b * nb_gemv / nb_total;
    long long incl   = (b + 1) * nb_gemv / nb_total;
    if (incl > before) {
        // ---- GEMV block ----
        int node = (int)before * 8 + (threadIdx.x >> 5);
        int lane = threadIdx.x & 31;
        if (node >= n_nodes) return;

        const float4* xr = reinterpret_cast<const float4*>(x + (size_t)node * GN_N_FEAT);
        const float4* wv = reinterpret_cast<const float4*>(W);

        float s = 0.f;
#pragma unroll
        for (int i = 0; i < 2; i++) {
            float4 va = xr[lane + 32 * i];
            float4 vb = __ldg(&wv[lane + 32 * i]);
            s += va.x * vb.x + va.y * vb.y + va.z * vb.z + va.w * vb.w;
        }
#pragma unroll
        for (int o = 16; o; o >>= 1) s += __shfl_down_sync(0xFFFFFFFFu, s, o);

        if (lane == 0) h[node] = s;
    } else {
        // ---- DEG block: 8 edges/thread ----
        int did = (int)(b - before);
        long long e0 = ((long long)did * 256 + threadIdx.x) * 8;
        if (e0 >= E) return;
        if (e0 + 7 < E) {
            float4 w0 = *reinterpret_cast<const float4*>(attrs + e0);
            float4 w1 = *reinterpret_cast<const float4*>(attrs + e0 + 4);
            int c[8];
            if (g_is64) {
                const long long* p = (const long long*)ei + E;
#pragma unroll
                for (int j = 0; j < 4; j++) {
                    longlong2 cc = *reinterpret_cast<const longlong2*>(p + e0 + 2 * j);
                    c[2 * j] = (int)cc.x; c[2 * j + 1] = (int)cc.y;
                }
            } else {
                const int* p = (const int*)ei + E;
                int4 ca = *reinterpret_cast<const int4*>(p + e0);
                int4 cb = *reinterpret_cast<const int4*>(p + e0 + 4);
                c[0] = ca.x; c[1] = ca.y; c[2] = ca.z; c[3] = ca.w;
                c[4] = cb.x; c[5] = cb.y; c[6] = cb.z; c[7] = cb.w;
            }
            atomicAdd(&degacc[c[0]], w0.x);
            atomicAdd(&degacc[c[1]], w0.y);
            atomicAdd(&degacc[c[2]], w0.z);
            atomicAdd(&degacc[c[3]], w0.w);
            atomicAdd(&degacc[c[4]], w1.x);
            atomicAdd(&degacc[c[5]], w1.y);
            atomicAdd(&degacc[c[6]], w1.z);
            atomicAdd(&degacc[c[7]], w1.w);
        } else {
            for (long long e = e0; e < E; e++) {
                int c = g_is64 ? (int)((const long long*)ei)[E + e]
                               : ((const int*)ei)[E + e];
                atomicAdd(&degacc[c], attrs[e]);
            }
        }
    }
}

// ---------------------------------------------------------------------------
// Kernel C: dis = rsqrt(degacc + 1) ; a = dis*h ; out = 0 ; re-zero degacc
// ---------------------------------------------------------------------------
__global__ void k_rsqrt(float* __restrict__ degacc,
                        float* __restrict__ dis,
                        const float* __restrict__ h,
                        float* __restrict__ a,
                        float* __restrict__ out,
                        int n_nodes) {
    int i = blockIdx.x * blockDim.x + threadIdx.x;
    if (i < n_nodes) {
        float d = degacc[i] + 1.0f;
        degacc[i] = 0.0f;
        float di = rsqrtf(d);
        dis[i] = di;
        a[i]   = di * h[i];
        out[i] = 0.0f;
    }
}

// ---------------------------------------------------------------------------
// Kernel D: out[col] += a[row] * attrs   (8 edges/thread, 1 gather/edge)
// All 8 gathers issued before any RED -> deep MLP, hides L2 gather latency.
// ---------------------------------------------------------------------------
__global__ void k_msg(const void* __restrict__ ei,
                      const float* __restrict__ attrs,
                      const float* __restrict__ a,
                      float* __restrict__ out,
                      int E) {
    long long e0 = ((long long)blockIdx.x * blockDim.x + threadIdx.x) * 8;
    if (e0 >= E) return;
    if (e0 + 7 < E) {
        float4 w0 = *reinterpret_cast<const float4*>(attrs + e0);
        float4 w1 = *reinterpret_cast<const float4*>(attrs + e0 + 4);
        int r[8], c[8];
        if (g_is64) {
            const long long* pr = (const long long*)ei;
            const long long* pc = pr + E;
#pragma unroll
            for (int j = 0; j < 4; j++) {
                longlong2 rr = *reinterpret_cast<const longlong2*>(pr + e0 + 2 * j);
                longlong2 cc = *reinterpret_cast<const longlong2*>(pc + e0 + 2 * j);
                r[2 * j] = (int)rr.x; r[2 * j + 1] = (int)rr.y;
                c[2 * j] = (int)cc.x; c[2 * j + 1] = (int)cc.y;
            }
        } else {
            const int* pr = (const int*)ei;
            const int* pc = pr + E;
            int4 ra = *reinterpret_cast<const int4*>(pr + e0);
            int4 rb = *reinterpret_cast<const int4*>(pr + e0 + 4);
            int4 ca = *reinterpret_cast<const int4*>(pc + e0);
            int4 cb = *reinterpret_cast<const int4*>(pc + e0 + 4);
            r[0] = ra.x; r[1] = ra.y; r[2] = ra.z; r[3] = ra.w;
            r[4] = rb.x; r[5] = rb.y; r[6] = rb.z; r[7] = rb.w;
            c[0] = ca.x; c[1] = ca.y; c[2] = ca.z; c[3] = ca.w;
            c[4] = cb.x; c[5] = cb.y; c[6] = cb.z; c[7] = cb.w;
        }
        float av[8];
#pragma unroll
        for (int j = 0; j < 8; j++) av[j] = __ldg(&a[r[j]]);  // 8 independent gathers
        float wv[8] = {w0.x, w0.y, w0.z, w0.w, w1.x, w1.y, w1.z, w1.w};
#pragma unroll
        for (int j = 0; j < 8; j++) atomicAdd(&out[c[j]], av[j] * wv[j]);
    } else {
        for (long long e = e0; e < E; e++) {
            int r, c;
            if (g_is64) {
                r = (int)((const long long*)ei)[e];
                c = (int)((const long long*)ei)[E + e];
            } else {
                r = ((const int*)ei)[e];
                c = ((const int*)ei)[E + e];
            }
            atomicAdd(&out[c], a[r] * attrs[e]);
        }
    }
}

// ---------------------------------------------------------------------------
// Kernel E: out = Mish(dis*(out + a) + b)
// ---------------------------------------------------------------------------
__global__ void k_finish(float* __restrict__ out,
                         const float* __restrict__ dis,
                         const float* __restrict__ a,
                         const float* __restrict__ b,
                         int n_nodes) {
    int i = blockIdx.x * blockDim.x + threadIdx.x;
    if (i < n_nodes) {
        float t = dis[i] * (out[i] + a[i]) + b[0];
        float sp = (t > 20.f) ? t : log1pf(expf(t));
        out[i] = t * tanhf(sp);
    }
}

extern "C" void kernel_launch(void* const* d_in, const int* in_sizes, int n_in,
                              void* d_out, int out_size) {
    // identify inputs by element count (descending: x > edge > attrs > W > b)
    int ix = 0, ie = 1, ia = 2, iw = 3, ib = 4;
    {
        long long best = -1;
        for (int i = 0; i < n_in; i++) if ((long long)in_sizes[i] > best) { best = in_sizes[i]; ix = i; }
        long long second = -1;
        for (int i = 0; i < n_in; i++) if (i != ix && (long long)in_sizes[i] > second) { second = in_sizes[i]; ie = i; }
        long long third = -1;
        for (int i = 0; i < n_in; i++) if (i != ix && i != ie && (long long)in_sizes[i] > third) { third = in_sizes[i]; ia = i; }
        long long fourth = -1;
        for (int i = 0; i < n_in; i++) if (i != ix && i != ie && i != ia && (long long)in_sizes[i] > fourth) { fourth = in_sizes[i]; iw = i; }
        for (int i = 0; i < n_in; i++) if (i != ix && i != ie && i != ia && i != iw) ib = i;
    }

    const float* x    = (const float*)d_in[ix];
    const void*  ei   = d_in[ie];
    const float* atts = (const float*)d_in[ia];
    const float* W    = (const float*)d_in[iw];
    const float* b    = (const float*)d_in[ib];
    float*       out  = (float*)d_out;

    const int E = in_sizes[ia];                 // 12.8M
    const int N = in_sizes[ix] / GN_N_FEAT;     // 200k

    float* h;    cudaGetSymbolAddress((void**)&h,    g_h);
    float* dis;  cudaGetSymbolAddress((void**)&dis,  g_dis);
    float* a;    cudaGetSymbolAddress((void**)&a,    g_a);
    float* dacc; cudaGetSymbolAddress((void**)&dacc, g_degacc);

    // 0: dtype detection (1 block, trivial)
    k_detect<<<1, 256>>>((const long long*)ei, E, N);

    // 1: fused GEMV + degree scatter (interleaved block types)
    {
        int nb_gemv = (N + 7) / 8;
        int nb_deg  = (E + 2047) / 2048;   // 256 thr * 8 edges
        int nb_total = nb_gemv + nb_deg;
        k_fused1<<<nb_total, 256>>>(x, W, h, dacc, N, ei, atts, E,
                                    nb_gemv, nb_total);
    }
    // 2: rsqrt + a = dis*h + out init (+ re-zero deg accumulator)
    k_rsqrt<<<(N + 255) / 256, 256>>>(dacc, dis, h, a, out, N);

    // 3: edge messages (8 edges/thread, 1 gather/edge)
    {
        long long octs = ((long long)E + 7) / 8;
        int blocks = (int)((octs + 255) / 256);
        k_msg<<<blocks, 256>>>(ei, atts, a, out, E);
    }
    // 4: scale + self loop + bias + Mish
    k_finish<<<(N + 255) / 256, 256>>>(out, dis, a, b, N);
}